// round 11
// baseline (speedup 1.0000x reference)
#include <cuda_runtime.h>
#include <cuda_fp16.h>
#include <math.h>
#include <stdint.h>

#define NN 100000
#define EE 1600000
#define IN_DIM 128
#define OUT_DIM 64
#define ASTR 132   // padded row stride (floats): conflict-free fragment LDS, 16B-aligned rows
#define CAP 64     // padded-CSR capacity per node (P(deg>=64) ~ 2e-22 for Poisson(16))

// ---------------- scratch (static __device__, no allocs; zero-initialized) ----------------
__device__ __align__(16) __half g_zh[(size_t)NN * OUT_DIM]; // 12.8 MB (z in fp16)
__device__ float g_ss[NN];                 // s_src per node
__device__ float g_sd[NN];                 // s_dst per node
__device__ int   g_cnt[NN];                // per-dst degree (atomic cursor); re-zeroed by k_node
__device__ int   g_pad[(size_t)NN * CAP];  // padded CSR: src ids per dst (25.6 MB)

// ---------------- helpers ----------------
__device__ __forceinline__ uint32_t f2tf32(float x) {
    uint32_t u;
    asm("cvt.rna.tf32.f32 %0, %1;" : "=r"(u) : "f"(x));
    return u;
}

__device__ __forceinline__ void mma_tf32(float c[4], uint32_t a0, uint32_t a1,
                                         uint32_t a2, uint32_t a3,
                                         uint32_t b0, uint32_t b1) {
    asm volatile(
        "mma.sync.aligned.m16n8k8.row.col.f32.tf32.tf32.f32 "
        "{%0,%1,%2,%3}, {%4,%5,%6,%7}, {%8,%9}, {%0,%1,%2,%3};"
        : "+f"(c[0]), "+f"(c[1]), "+f"(c[2]), "+f"(c[3])
        : "r"(a0), "r"(a1), "r"(a2), "r"(a3), "r"(b0), "r"(b1));
}

// packed f32x2 FMA: c += s * v (2 lanes per instruction; FFMA2, sm_100+ base PTX)
__device__ __forceinline__ void ffma2(float2& c, float s, float2 v) {
    asm("{\n\t"
        ".reg .b64 ra, rb, rc;\n\t"
        "mov.b64 ra, {%2, %2};\n\t"
        "mov.b64 rb, {%3, %4};\n\t"
        "mov.b64 rc, {%0, %1};\n\t"
        "fma.rn.f32x2 rc, ra, rb, rc;\n\t"
        "mov.b64 {%0, %1}, rc;\n\t"
        "}"
        : "+f"(c.x), "+f"(c.y)
        : "f"(s), "f"(v.x), "f"(v.y));
}

// ---------------- fused GEMM + bucket kernel ----------------
// Role-interleaved blocks: idx%3==2 -> bucket (CSR build), else -> gemm tile.
// The two roles touch disjoint data, so they run concurrently across SMs.
__global__ __launch_bounds__(256) void k_gemm_bucket(
    const float* __restrict__ h, const float* __restrict__ W,
    const float* __restrict__ a,
    const int* __restrict__ src, const int* __restrict__ dst,
    int N, int E, int NGB, int NBK)
{
    extern __shared__ __align__(16) float smem[];
    int tid = threadIdx.x;
    int idx = blockIdx.x;
    int r = idx % 3;

    if (r == 2) {
        // ---- bucket role: padded-CSR build, grid-stride over edges ----
        int bucket_id = idx / 3;
        if (bucket_id >= NBK) return;
        int stride = NBK * 256;
        for (int i = bucket_id * 256 + tid; i < E; i += stride) {
            int d = dst[i];
            int p = atomicAdd(&g_cnt[d], 1);
            if (p < CAP) g_pad[(size_t)d * CAP + p] = src[i];
        }
        return;
    }

    // ---- gemm role ----
    int gemm_id = (idx / 3) * 2 + r;
    if (gemm_id >= NGB) return;

    float* As  = smem;                    // [128][ASTR] tf32 bits
    float* Ws  = smem + 128 * ASTR;       // [64][ASTR]  tf32 bits
    float* ash = smem + 192 * ASTR;       // [128] fp32

    int node0 = gemm_id * 128;

    if (tid < 2 * OUT_DIM) ash[tid] = a[tid];

    // stage A (h rows), converting to tf32
    for (int i = tid; i < 128 * 32; i += 256) {
        int rr = i >> 5;
        int q4 = i & 31;
        int n = node0 + rr;
        float4 v = make_float4(0.f, 0.f, 0.f, 0.f);
        if (n < N) v = *(const float4*)(h + (size_t)n * IN_DIM + q4 * 4);
        float4 t;
        t.x = __uint_as_float(f2tf32(v.x));
        t.y = __uint_as_float(f2tf32(v.y));
        t.z = __uint_as_float(f2tf32(v.z));
        t.w = __uint_as_float(f2tf32(v.w));
        *(float4*)(As + rr * ASTR + q4 * 4) = t;
    }
    // stage B (W rows), converting to tf32
    for (int i = tid; i < 64 * 32; i += 256) {
        int rr = i >> 5;
        int q4 = i & 31;
        float4 v = *(const float4*)(W + (size_t)rr * IN_DIM + q4 * 4);
        float4 t;
        t.x = __uint_as_float(f2tf32(v.x));
        t.y = __uint_as_float(f2tf32(v.y));
        t.z = __uint_as_float(f2tf32(v.z));
        t.w = __uint_as_float(f2tf32(v.w));
        *(float4*)(Ws + rr * ASTR + q4 * 4) = t;
    }
    __syncthreads();

    int wid = tid >> 5;
    int lane = tid & 31;
    int g = lane >> 2;        // groupID: row within fragment
    int tg = lane & 3;        // threadID in group

    float acc[8][4];
    #pragma unroll
    for (int t = 0; t < 8; t++)
        #pragma unroll
        for (int j = 0; j < 4; j++) acc[t][j] = 0.f;

    const float* arow = As + (wid * 16 + g) * ASTR + tg;
    const float* brow = Ws + g * ASTR + tg;

    #pragma unroll
    for (int ks = 0; ks < 16; ks++) {
        int k0 = ks * 8;
        uint32_t a0 = __float_as_uint(arow[k0]);
        uint32_t a1 = __float_as_uint(arow[8 * ASTR + k0]);
        uint32_t a2 = __float_as_uint(arow[k0 + 4]);
        uint32_t a3 = __float_as_uint(arow[8 * ASTR + k0 + 4]);
        #pragma unroll
        for (int t = 0; t < 8; t++) {
            uint32_t b0 = __float_as_uint(brow[t * 8 * ASTR + k0]);
            uint32_t b1 = __float_as_uint(brow[t * 8 * ASTR + k0 + 4]);
            mma_tf32(acc[t], a0, a1, a2, a3, b0, b1);
        }
    }

    // epilogue: rows r0 = node0+16w+g, r1 = r0+8; thread owns cols 8t+2tg, 8t+2tg+1
    int r0 = node0 + wid * 16 + g;
    int r1 = r0 + 8;
    float p0 = 0.f, q0 = 0.f, p1 = 0.f, q1 = 0.f;
    #pragma unroll
    for (int t = 0; t < 8; t++) {
        int c = 8 * t + 2 * tg;
        float av0 = ash[c], av1 = ash[c + 1];
        float bv0 = ash[OUT_DIM + c], bv1 = ash[OUT_DIM + c + 1];
        if (r0 < N) *(__half2*)(g_zh + (size_t)r0 * OUT_DIM + c) =
            __floats2half2_rn(acc[t][0], acc[t][1]);
        if (r1 < N) *(__half2*)(g_zh + (size_t)r1 * OUT_DIM + c) =
            __floats2half2_rn(acc[t][2], acc[t][3]);
        p0 = fmaf(acc[t][0], av0, fmaf(acc[t][1], av1, p0));
        q0 = fmaf(acc[t][0], bv0, fmaf(acc[t][1], bv1, q0));
        p1 = fmaf(acc[t][2], av0, fmaf(acc[t][3], av1, p1));
        q1 = fmaf(acc[t][2], bv0, fmaf(acc[t][3], bv1, q1));
    }
    #pragma unroll
    for (int off = 1; off < 4; off <<= 1) {
        p0 += __shfl_xor_sync(0xffffffffu, p0, off);
        q0 += __shfl_xor_sync(0xffffffffu, q0, off);
        p1 += __shfl_xor_sync(0xffffffffu, p1, off);
        q1 += __shfl_xor_sync(0xffffffffu, q1, off);
    }
    if (tg == 0) {
        if (r0 < N) { g_ss[r0] = p0; g_sd[r0] = q0; }
        if (r1 < N) { g_ss[r1] = p1; g_sd[r1] = q1; }
    }
}

// ---------------- aggregation kernel ----------------
// one warp per dst node; softmax without max-shift (|score| <~ 2);
// half-warp 2-edge split: lane handles dims (lane&15)*4..+3 of edge j+(lane>>4).
// resets g_cnt[node] = 0 for the next launch (statics start zeroed).
__global__ __launch_bounds__(256) void k_node(float* __restrict__ out, int N)
{
    int warp = (blockIdx.x * blockDim.x + threadIdx.x) >> 5;
    int lane = threadIdx.x & 31;
    if (warp >= N) return;
    int node = warp;
    int deg = min(g_cnt[node], CAP);
    if (lane == 0) g_cnt[node] = 0;   // reset for next launch (read happened above)
    const int* lst = g_pad + (size_t)node * CAP;

    int hh  = lane >> 4;    // which edge of the pair
    int sub = lane & 15;    // dim group: dims sub*4 .. sub*4+3
    float2 accA = make_float2(0.f, 0.f);   // dims sub*4+0, +1
    float2 accB = make_float2(0.f, 0.f);   // dims sub*4+2, +3
    float den = 0.f;

    if (deg > 0 && deg <= 32) {
        float sd = g_sd[node];
        bool act = lane < deg;
        int sreg = act ? lst[lane] : 0;
        float v = act ? g_ss[sreg] + sd : 0.f;
        v = (v >= 0.f) ? v : 0.01f * v;
        float ex = act ? __expf(v) : 0.f;
        den = ex;
        #pragma unroll
        for (int off = 16; off; off >>= 1)
            den += __shfl_xor_sync(0xffffffffu, den, off);

        for (int j = 0; j < deg; j += 2) {
            int jj = j + hh;
            int s   = __shfl_sync(0xffffffffu, sreg, jj);
            float e = __shfl_sync(0xffffffffu, ex, jj);
            if (jj < deg) {
                uint2 raw = *(const uint2*)(g_zh + (size_t)s * OUT_DIM + sub * 4);
                float2 lo = __half22float2(*(const __half2*)&raw.x);
                float2 hi = __half22float2(*(const __half2*)&raw.y);
                ffma2(accA, e, lo);
                ffma2(accB, e, hi);
            }
        }
        // combine the two half-warp partials (both halves end with the full sum)
        accA.x += __shfl_xor_sync(0xffffffffu, accA.x, 16);
        accA.y += __shfl_xor_sync(0xffffffffu, accA.y, 16);
        accB.x += __shfl_xor_sync(0xffffffffu, accB.x, 16);
        accB.y += __shfl_xor_sync(0xffffffffu, accB.y, 16);
    } else if (deg > 32) {
        // rare path: combined denom + accumulation, lane owns dims (2*lane, 2*lane+1)
        float sd = g_sd[node];
        float2 acc = make_float2(0.f, 0.f);
        float denl = 0.f;
        for (int base = 0; base < deg; base += 32) {
            int i = base + lane;
            int sreg = 0;
            float ex = 0.f;
            if (i < deg) {
                sreg = lst[i];
                float v = g_ss[sreg] + sd;
                v = (v >= 0.f) ? v : 0.01f * v;
                ex = __expf(v);
                denl += ex;
            }
            int cnt = min(32, deg - base);
            #pragma unroll 8
            for (int j = 0; j < cnt; j++) {
                int s = __shfl_sync(0xffffffffu, sreg, j);
                float ej = __shfl_sync(0xffffffffu, ex, j);
                float2 zv = __half22float2(*(const __half2*)(g_zh + (size_t)s * OUT_DIM + lane * 2));
                acc.x = fmaf(ej, zv.x, acc.x);
                acc.y = fmaf(ej, zv.y, acc.y);
            }
        }
        den = denl;
        #pragma unroll
        for (int off = 16; off; off >>= 1)
            den += __shfl_xor_sync(0xffffffffu, den, off);
        // redistribute: lane owns dims (2*lane, 2*lane+1); convert to split layout
        // via shared-free shuffle: target lane for dim d group sub*4 is sub = d>>2.
        // dims 2*lane   -> sub = lane>>1, slot (lane&1)*2
        // simplest: write through registers by exchanging via shfl:
        // lane L needs dims sub*4..+3 = dims held by lanes 2*sub and 2*sub+1.
        float xA = __shfl_sync(0xffffffffu, acc.x, 2 * sub);      // dim 4*sub
        float yA = __shfl_sync(0xffffffffu, acc.y, 2 * sub);      // dim 4*sub+1
        float xB = __shfl_sync(0xffffffffu, acc.x, 2 * sub + 1);  // dim 4*sub+2
        float yB = __shfl_sync(0xffffffffu, acc.y, 2 * sub + 1);  // dim 4*sub+3
        accA = make_float2(xA, yA);
        accB = make_float2(xB, yB);
    }

    if (lane < 16) {
        if (deg > 0) {
            float inv = 1.f / den;
            accA.x *= inv; accA.y *= inv;
            accB.x *= inv; accB.y *= inv;
        }
        // fused ELU
        accA.x = (accA.x > 0.f) ? accA.x : expm1f(accA.x);
        accA.y = (accA.y > 0.f) ? accA.y : expm1f(accA.y);
        accB.x = (accB.x > 0.f) ? accB.x : expm1f(accB.x);
        accB.y = (accB.y > 0.f) ? accB.y : expm1f(accB.y);
        *(float4*)(out + (size_t)node * OUT_DIM + sub * 4) =
            make_float4(accA.x, accA.y, accB.x, accB.y);
    }
}

// ---------------- launch ----------------
extern "C" void kernel_launch(void* const* d_in, const int* in_sizes, int n_in,
                              void* d_out, int out_size) {
    const float* h   = (const float*)d_in[0];
    const int*   src = (const int*)d_in[1];
    const int*   dst = (const int*)d_in[2];
    const float* W   = (const float*)d_in[3];
    const float* a   = (const float*)d_in[4];
    float* out = (float*)d_out;

    int N = in_sizes[0] / IN_DIM;   // 100000
    int E = in_sizes[1];            // 1600000

    int NGB = (N + 127) / 128;      // 782 gemm blocks
    int NBK = (NGB + 1) / 2;        // 391 bucket blocks
    int TOTAL = NGB + NBK;          // 1173 (pattern: idx%3==2 -> bucket)

    int smem_bytes = (192 * ASTR + 128) * sizeof(float);  // ~101.9 KB
    cudaFuncSetAttribute(k_gemm_bucket, cudaFuncAttributeMaxDynamicSharedMemorySize, smem_bytes);

    k_gemm_bucket<<<TOTAL, 256, smem_bytes>>>(h, W, a, src, dst, N, E, NGB, NBK);
    k_node<<<(N * 32 + 255) / 256, 256>>>(out, N);
}

// round 13
// speedup vs baseline: 1.0515x; 1.0515x over previous
#include <cuda_runtime.h>
#include <cuda_fp16.h>
#include <math.h>
#include <stdint.h>

#define NN 100000
#define EE 1600000
#define IN_DIM 128
#define OUT_DIM 64
#define ASTR 132   // padded row stride (floats): conflict-free fragment LDS, 16B-aligned rows
#define CAP 64     // padded-CSR capacity per node (P(deg>=64) ~ 2e-22 for Poisson(16))

// ---------------- scratch (static __device__, no allocs; zero-initialized) ----------------
__device__ __align__(16) __half g_zh[(size_t)NN * OUT_DIM]; // 12.8 MB (z in fp16)
__device__ float g_ss[NN];                 // s_src per node
__device__ float g_sd[NN];                 // s_dst per node
__device__ int   g_cnt[NN];                // per-dst degree (atomic cursor); re-zeroed by k_node
__device__ int   g_pad[(size_t)NN * CAP];  // padded CSR: src ids per dst (25.6 MB)

// ---------------- helpers ----------------
__device__ __forceinline__ uint32_t f2tf32(float x) {
    uint32_t u;
    asm("cvt.rna.tf32.f32 %0, %1;" : "=r"(u) : "f"(x));
    return u;
}

__device__ __forceinline__ void mma_tf32(float c[4], uint32_t a0, uint32_t a1,
                                         uint32_t a2, uint32_t a3,
                                         uint32_t b0, uint32_t b1) {
    asm volatile(
        "mma.sync.aligned.m16n8k8.row.col.f32.tf32.tf32.f32 "
        "{%0,%1,%2,%3}, {%4,%5,%6,%7}, {%8,%9}, {%0,%1,%2,%3};"
        : "+f"(c[0]), "+f"(c[1]), "+f"(c[2]), "+f"(c[3])
        : "r"(a0), "r"(a1), "r"(a2), "r"(a3), "r"(b0), "r"(b1));
}

// ---------------- fused GEMM + bucket kernel ----------------
// Role-interleaved blocks: idx%3==2 -> bucket (CSR build), else -> gemm tile.
// The two roles touch disjoint data, so they run concurrently across SMs.
__global__ __launch_bounds__(256) void k_gemm_bucket(
    const float* __restrict__ h, const float* __restrict__ W,
    const float* __restrict__ a,
    const int* __restrict__ src, const int* __restrict__ dst,
    int N, int E, int NGB, int NBK)
{
    extern __shared__ __align__(16) float smem[];
    int tid = threadIdx.x;
    int idx = blockIdx.x;
    int r = idx % 3;

    if (r == 2) {
        // ---- bucket role: padded-CSR build, grid-stride over edges ----
        int bucket_id = idx / 3;
        if (bucket_id >= NBK) return;
        int stride = NBK * 256;
        for (int i = bucket_id * 256 + tid; i < E; i += stride) {
            int d = dst[i];
            int p = atomicAdd(&g_cnt[d], 1);
            if (p < CAP) g_pad[(size_t)d * CAP + p] = src[i];
        }
        return;
    }

    // ---- gemm role ----
    int gemm_id = (idx / 3) * 2 + r;
    if (gemm_id >= NGB) return;

    float* As  = smem;                    // [128][ASTR] tf32 bits
    float* Ws  = smem + 128 * ASTR;       // [64][ASTR]  tf32 bits
    float* ash = smem + 192 * ASTR;       // [128] fp32

    int node0 = gemm_id * 128;

    if (tid < 2 * OUT_DIM) ash[tid] = a[tid];

    // stage A (h rows), converting to tf32
    for (int i = tid; i < 128 * 32; i += 256) {
        int rr = i >> 5;
        int q4 = i & 31;
        int n = node0 + rr;
        float4 v = make_float4(0.f, 0.f, 0.f, 0.f);
        if (n < N) v = *(const float4*)(h + (size_t)n * IN_DIM + q4 * 4);
        float4 t;
        t.x = __uint_as_float(f2tf32(v.x));
        t.y = __uint_as_float(f2tf32(v.y));
        t.z = __uint_as_float(f2tf32(v.z));
        t.w = __uint_as_float(f2tf32(v.w));
        *(float4*)(As + rr * ASTR + q4 * 4) = t;
    }
    // stage B (W rows), converting to tf32
    for (int i = tid; i < 64 * 32; i += 256) {
        int rr = i >> 5;
        int q4 = i & 31;
        float4 v = *(const float4*)(W + (size_t)rr * IN_DIM + q4 * 4);
        float4 t;
        t.x = __uint_as_float(f2tf32(v.x));
        t.y = __uint_as_float(f2tf32(v.y));
        t.z = __uint_as_float(f2tf32(v.z));
        t.w = __uint_as_float(f2tf32(v.w));
        *(float4*)(Ws + rr * ASTR + q4 * 4) = t;
    }
    __syncthreads();

    int wid = tid >> 5;
    int lane = tid & 31;
    int g = lane >> 2;        // groupID: row within fragment
    int tg = lane & 3;        // threadID in group

    float acc[8][4];
    #pragma unroll
    for (int t = 0; t < 8; t++)
        #pragma unroll
        for (int j = 0; j < 4; j++) acc[t][j] = 0.f;

    const float* arow = As + (wid * 16 + g) * ASTR + tg;
    const float* brow = Ws + g * ASTR + tg;

    #pragma unroll
    for (int ks = 0; ks < 16; ks++) {
        int k0 = ks * 8;
        uint32_t a0 = __float_as_uint(arow[k0]);
        uint32_t a1 = __float_as_uint(arow[8 * ASTR + k0]);
        uint32_t a2 = __float_as_uint(arow[k0 + 4]);
        uint32_t a3 = __float_as_uint(arow[8 * ASTR + k0 + 4]);
        #pragma unroll
        for (int t = 0; t < 8; t++) {
            uint32_t b0 = __float_as_uint(brow[t * 8 * ASTR + k0]);
            uint32_t b1 = __float_as_uint(brow[t * 8 * ASTR + k0 + 4]);
            mma_tf32(acc[t], a0, a1, a2, a3, b0, b1);
        }
    }

    // epilogue: rows r0 = node0+16w+g, r1 = r0+8; thread owns cols 8t+2tg, 8t+2tg+1
    int r0 = node0 + wid * 16 + g;
    int r1 = r0 + 8;
    float p0 = 0.f, q0 = 0.f, p1 = 0.f, q1 = 0.f;
    #pragma unroll
    for (int t = 0; t < 8; t++) {
        int c = 8 * t + 2 * tg;
        float av0 = ash[c], av1 = ash[c + 1];
        float bv0 = ash[OUT_DIM + c], bv1 = ash[OUT_DIM + c + 1];
        if (r0 < N) *(__half2*)(g_zh + (size_t)r0 * OUT_DIM + c) =
            __floats2half2_rn(acc[t][0], acc[t][1]);
        if (r1 < N) *(__half2*)(g_zh + (size_t)r1 * OUT_DIM + c) =
            __floats2half2_rn(acc[t][2], acc[t][3]);
        p0 = fmaf(acc[t][0], av0, fmaf(acc[t][1], av1, p0));
        q0 = fmaf(acc[t][0], bv0, fmaf(acc[t][1], bv1, q0));
        p1 = fmaf(acc[t][2], av0, fmaf(acc[t][3], av1, p1));
        q1 = fmaf(acc[t][2], bv0, fmaf(acc[t][3], bv1, q1));
    }
    #pragma unroll
    for (int off = 1; off < 4; off <<= 1) {
        p0 += __shfl_xor_sync(0xffffffffu, p0, off);
        q0 += __shfl_xor_sync(0xffffffffu, q0, off);
        p1 += __shfl_xor_sync(0xffffffffu, p1, off);
        q1 += __shfl_xor_sync(0xffffffffu, q1, off);
    }
    if (tg == 0) {
        if (r0 < N) { g_ss[r0] = p0; g_sd[r0] = q0; }
        if (r1 < N) { g_ss[r1] = p1; g_sd[r1] = q1; }
    }
}

// ---------------- aggregation kernel (R10-proven version + g_cnt reset) ----------------
// one warp per dst node: softmax (no max-shift needed: |score| <~ 2) +
// weighted aggregation + ELU; single gather pass, no atomics
__global__ __launch_bounds__(256) void k_node(float* __restrict__ out, int N)
{
    int warp = (blockIdx.x * blockDim.x + threadIdx.x) >> 5;
    int lane = threadIdx.x & 31;
    if (warp >= N) return;
    int node = warp;
    int deg = min(g_cnt[node], CAP);
    if (lane == 0) g_cnt[node] = 0;   // reset for next launch (statics start zeroed)
    const int* lst = g_pad + (size_t)node * CAP;
    float2 acc = make_float2(0.f, 0.f);
    float den = 0.f;

    if (deg > 0 && deg <= 32) {
        // fast path: whole segment resident in one warp pass
        float sd = g_sd[node];
        bool act = lane < deg;
        int sreg = act ? lst[lane] : 0;
        float v = act ? g_ss[sreg] + sd : 0.f;
        v = (v >= 0.f) ? v : 0.01f * v;
        float ex = act ? __expf(v) : 0.f;
        den = ex;
        #pragma unroll
        for (int off = 16; off; off >>= 1)
            den += __shfl_xor_sync(0xffffffffu, den, off);
        #pragma unroll 8
        for (int j = 0; j < deg; j++) {
            int s = __shfl_sync(0xffffffffu, sreg, j);
            float ej = __shfl_sync(0xffffffffu, ex, j);
            float2 zv = __half22float2(*(const __half2*)(g_zh + (size_t)s * OUT_DIM + lane * 2));
            acc.x = fmaf(ej, zv.x, acc.x);
            acc.y = fmaf(ej, zv.y, acc.y);
        }
    } else if (deg > 32) {
        // single combined pass: denom + weighted accumulation
        float sd = g_sd[node];
        float denl = 0.f;
        for (int base = 0; base < deg; base += 32) {
            int i = base + lane;
            int sreg = 0;
            float ex = 0.f;
            if (i < deg) {
                sreg = lst[i];
                float v = g_ss[sreg] + sd;
                v = (v >= 0.f) ? v : 0.01f * v;
                ex = __expf(v);
                denl += ex;
            }
            int cnt = min(32, deg - base);
            #pragma unroll 8
            for (int j = 0; j < cnt; j++) {
                int s = __shfl_sync(0xffffffffu, sreg, j);
                float ej = __shfl_sync(0xffffffffu, ex, j);
                float2 zv = __half22float2(*(const __half2*)(g_zh + (size_t)s * OUT_DIM + lane * 2));
                acc.x = fmaf(ej, zv.x, acc.x);
                acc.y = fmaf(ej, zv.y, acc.y);
            }
        }
        den = denl;
        #pragma unroll
        for (int off = 16; off; off >>= 1)
            den += __shfl_xor_sync(0xffffffffu, den, off);
    }

    if (deg > 0) {
        float inv = 1.f / den;
        acc.x *= inv;
        acc.y *= inv;
    }
    // fused ELU; zero-degree nodes write elu(0)=0
    acc.x = (acc.x > 0.f) ? acc.x : expm1f(acc.x);
    acc.y = (acc.y > 0.f) ? acc.y : expm1f(acc.y);
    *(float2*)(out + (size_t)node * OUT_DIM + lane * 2) = acc;
}

// ---------------- launch ----------------
extern "C" void kernel_launch(void* const* d_in, const int* in_sizes, int n_in,
                              void* d_out, int out_size) {
    const float* h   = (const float*)d_in[0];
    const int*   src = (const int*)d_in[1];
    const int*   dst = (const int*)d_in[2];
    const float* W   = (const float*)d_in[3];
    const float* a   = (const float*)d_in[4];
    float* out = (float*)d_out;

    int N = in_sizes[0] / IN_DIM;   // 100000
    int E = in_sizes[1];            // 1600000

    int NGB = (N + 127) / 128;      // 782 gemm blocks
    int NBK = (NGB + 1) / 2;        // 391 bucket blocks
    int TOTAL = NGB + NBK;          // 1173 (pattern: idx%3==2 -> bucket)

    int smem_bytes = (192 * ASTR + 128) * sizeof(float);  // ~101.9 KB
    cudaFuncSetAttribute(k_gemm_bucket, cudaFuncAttributeMaxDynamicSharedMemorySize, smem_bytes);

    k_gemm_bucket<<<TOTAL, 256, smem_bytes>>>(h, W, a, src, dst, N, E, NGB, NBK);
    k_node<<<(N * 32 + 255) / 256, 256>>>(out, N);
}

// round 14
// speedup vs baseline: 1.8778x; 1.7858x over previous
#include <cuda_runtime.h>
#include <cuda_fp16.h>
#include <math.h>
#include <stdint.h>

#define NN 100000
#define EE 1600000
#define IN_DIM 128
#define OUT_DIM 64
#define ASTR 132   // padded row stride (floats): conflict-free fragment LDS, 16B-aligned rows
#define CAP 64     // padded-CSR capacity per node (P(deg>=64) ~ 2e-22 for Poisson(16))

// ---------------- scratch (static __device__, no allocs; zero-initialized) ----------------
__device__ __align__(16) __half g_zh[(size_t)NN * OUT_DIM]; // 12.8 MB (z in fp16)
__device__ float g_ss[NN];                 // s_src per node
__device__ float g_sd[NN];                 // s_dst per node
__device__ int   g_cnt[NN];                // per-dst degree (atomic cursor); zeroed by k_zero
__device__ int   g_pad[(size_t)NN * CAP];  // padded CSR: src ids per dst (25.6 MB)

// ---------------- helpers ----------------
__device__ __forceinline__ uint32_t f2tf32(float x) {
    uint32_t u;
    asm("cvt.rna.tf32.f32 %0, %1;" : "=r"(u) : "f"(x));
    return u;
}

__device__ __forceinline__ void mma_tf32(float c[4], uint32_t a0, uint32_t a1,
                                         uint32_t a2, uint32_t a3,
                                         uint32_t b0, uint32_t b1) {
    asm volatile(
        "mma.sync.aligned.m16n8k8.row.col.f32.tf32.tf32.f32 "
        "{%0,%1,%2,%3}, {%4,%5,%6,%7}, {%8,%9}, {%0,%1,%2,%3};"
        : "+f"(c[0]), "+f"(c[1]), "+f"(c[2]), "+f"(c[3])
        : "r"(a0), "r"(a1), "r"(a2), "r"(a3), "r"(b0), "r"(b1));
}

// ---------------- kernels ----------------

__global__ void k_zero(int N) {
    int i = blockIdx.x * blockDim.x + threadIdx.x;
    int stride = gridDim.x * blockDim.x;
    for (; i < N; i += stride) g_cnt[i] = 0;
}

// ---------------- fused GEMM + bucket kernel ----------------
// Role-interleaved blocks: idx%3==2 -> bucket (CSR build), else -> gemm tile.
// The two roles touch disjoint data, so they run concurrently across SMs.
__global__ __launch_bounds__(256) void k_gemm_bucket(
    const float* __restrict__ h, const float* __restrict__ W,
    const float* __restrict__ a,
    const int* __restrict__ src, const int* __restrict__ dst,
    int N, int E, int NGB, int NBK)
{
    extern __shared__ __align__(16) float smem[];
    int tid = threadIdx.x;
    int idx = blockIdx.x;
    int r = idx % 3;

    if (r == 2) {
        // ---- bucket role: padded-CSR build, grid-stride over edges ----
        int bucket_id = idx / 3;
        if (bucket_id >= NBK) return;
        int stride = NBK * 256;
        for (int i = bucket_id * 256 + tid; i < E; i += stride) {
            int d = dst[i];
            int p = atomicAdd(&g_cnt[d], 1);
            if (p < CAP) g_pad[(size_t)d * CAP + p] = src[i];
        }
        return;
    }

    // ---- gemm role ----
    int gemm_id = (idx / 3) * 2 + r;
    if (gemm_id >= NGB) return;

    float* As  = smem;                    // [128][ASTR] tf32 bits
    float* Ws  = smem + 128 * ASTR;       // [64][ASTR]  tf32 bits
    float* ash = smem + 192 * ASTR;       // [128] fp32

    int node0 = gemm_id * 128;

    if (tid < 2 * OUT_DIM) ash[tid] = a[tid];

    // stage A (h rows), converting to tf32
    for (int i = tid; i < 128 * 32; i += 256) {
        int rr = i >> 5;
        int q4 = i & 31;
        int n = node0 + rr;
        float4 v = make_float4(0.f, 0.f, 0.f, 0.f);
        if (n < N) v = *(const float4*)(h + (size_t)n * IN_DIM + q4 * 4);
        float4 t;
        t.x = __uint_as_float(f2tf32(v.x));
        t.y = __uint_as_float(f2tf32(v.y));
        t.z = __uint_as_float(f2tf32(v.z));
        t.w = __uint_as_float(f2tf32(v.w));
        *(float4*)(As + rr * ASTR + q4 * 4) = t;
    }
    // stage B (W rows), converting to tf32
    for (int i = tid; i < 64 * 32; i += 256) {
        int rr = i >> 5;
        int q4 = i & 31;
        float4 v = *(const float4*)(W + (size_t)rr * IN_DIM + q4 * 4);
        float4 t;
        t.x = __uint_as_float(f2tf32(v.x));
        t.y = __uint_as_float(f2tf32(v.y));
        t.z = __uint_as_float(f2tf32(v.z));
        t.w = __uint_as_float(f2tf32(v.w));
        *(float4*)(Ws + rr * ASTR + q4 * 4) = t;
    }
    __syncthreads();

    int wid = tid >> 5;
    int lane = tid & 31;
    int g = lane >> 2;        // groupID: row within fragment
    int tg = lane & 3;        // threadID in group

    float acc[8][4];
    #pragma unroll
    for (int t = 0; t < 8; t++)
        #pragma unroll
        for (int j = 0; j < 4; j++) acc[t][j] = 0.f;

    const float* arow = As + (wid * 16 + g) * ASTR + tg;
    const float* brow = Ws + g * ASTR + tg;

    #pragma unroll
    for (int ks = 0; ks < 16; ks++) {
        int k0 = ks * 8;
        uint32_t a0 = __float_as_uint(arow[k0]);
        uint32_t a1 = __float_as_uint(arow[8 * ASTR + k0]);
        uint32_t a2 = __float_as_uint(arow[k0 + 4]);
        uint32_t a3 = __float_as_uint(arow[8 * ASTR + k0 + 4]);
        #pragma unroll
        for (int t = 0; t < 8; t++) {
            uint32_t b0 = __float_as_uint(brow[t * 8 * ASTR + k0]);
            uint32_t b1 = __float_as_uint(brow[t * 8 * ASTR + k0 + 4]);
            mma_tf32(acc[t], a0, a1, a2, a3, b0, b1);
        }
    }

    // epilogue: rows r0 = node0+16w+g, r1 = r0+8; thread owns cols 8t+2tg, 8t+2tg+1
    int r0 = node0 + wid * 16 + g;
    int r1 = r0 + 8;
    float p0 = 0.f, q0 = 0.f, p1 = 0.f, q1 = 0.f;
    #pragma unroll
    for (int t = 0; t < 8; t++) {
        int c = 8 * t + 2 * tg;
        float av0 = ash[c], av1 = ash[c + 1];
        float bv0 = ash[OUT_DIM + c], bv1 = ash[OUT_DIM + c + 1];
        if (r0 < N) *(__half2*)(g_zh + (size_t)r0 * OUT_DIM + c) =
            __floats2half2_rn(acc[t][0], acc[t][1]);
        if (r1 < N) *(__half2*)(g_zh + (size_t)r1 * OUT_DIM + c) =
            __floats2half2_rn(acc[t][2], acc[t][3]);
        p0 = fmaf(acc[t][0], av0, fmaf(acc[t][1], av1, p0));
        q0 = fmaf(acc[t][0], bv0, fmaf(acc[t][1], bv1, q0));
        p1 = fmaf(acc[t][2], av0, fmaf(acc[t][3], av1, p1));
        q1 = fmaf(acc[t][2], bv0, fmaf(acc[t][3], bv1, q1));
    }
    #pragma unroll
    for (int off = 1; off < 4; off <<= 1) {
        p0 += __shfl_xor_sync(0xffffffffu, p0, off);
        q0 += __shfl_xor_sync(0xffffffffu, q0, off);
        p1 += __shfl_xor_sync(0xffffffffu, p1, off);
        q1 += __shfl_xor_sync(0xffffffffu, q1, off);
    }
    if (tg == 0) {
        if (r0 < N) { g_ss[r0] = p0; g_sd[r0] = q0; }
        if (r1 < N) { g_ss[r1] = p1; g_sd[r1] = q1; }
    }
}

// ---------------- aggregation kernel (R10-proven version, NO g_cnt reset) ----------------
// one warp per dst node: softmax (no max-shift needed: |score| <~ 2) +
// weighted aggregation + ELU; single gather pass, no atomics
__global__ __launch_bounds__(256) void k_node(float* __restrict__ out, int N)
{
    int warp = (blockIdx.x * blockDim.x + threadIdx.x) >> 5;
    int lane = threadIdx.x & 31;
    if (warp >= N) return;
    int node = warp;
    int deg = min(g_cnt[node], CAP);
    const int* lst = g_pad + (size_t)node * CAP;
    float2 acc = make_float2(0.f, 0.f);
    float den = 0.f;

    if (deg > 0 && deg <= 32) {
        // fast path: whole segment resident in one warp pass
        float sd = g_sd[node];
        bool act = lane < deg;
        int sreg = act ? lst[lane] : 0;
        float v = act ? g_ss[sreg] + sd : 0.f;
        v = (v >= 0.f) ? v : 0.01f * v;
        float ex = act ? __expf(v) : 0.f;
        den = ex;
        #pragma unroll
        for (int off = 16; off; off >>= 1)
            den += __shfl_xor_sync(0xffffffffu, den, off);
        #pragma unroll 8
        for (int j = 0; j < deg; j++) {
            int s = __shfl_sync(0xffffffffu, sreg, j);
            float ej = __shfl_sync(0xffffffffu, ex, j);
            float2 zv = __half22float2(*(const __half2*)(g_zh + (size_t)s * OUT_DIM + lane * 2));
            acc.x = fmaf(ej, zv.x, acc.x);
            acc.y = fmaf(ej, zv.y, acc.y);
        }
    } else if (deg > 32) {
        // single combined pass: denom + weighted accumulation
        float sd = g_sd[node];
        float denl = 0.f;
        for (int base = 0; base < deg; base += 32) {
            int i = base + lane;
            int sreg = 0;
            float ex = 0.f;
            if (i < deg) {
                sreg = lst[i];
                float v = g_ss[sreg] + sd;
                v = (v >= 0.f) ? v : 0.01f * v;
                ex = __expf(v);
                denl += ex;
            }
            int cnt = min(32, deg - base);
            #pragma unroll 8
            for (int j = 0; j < cnt; j++) {
                int s = __shfl_sync(0xffffffffu, sreg, j);
                float ej = __shfl_sync(0xffffffffu, ex, j);
                float2 zv = __half22float2(*(const __half2*)(g_zh + (size_t)s * OUT_DIM + lane * 2));
                acc.x = fmaf(ej, zv.x, acc.x);
                acc.y = fmaf(ej, zv.y, acc.y);
            }
        }
        den = denl;
        #pragma unroll
        for (int off = 16; off; off >>= 1)
            den += __shfl_xor_sync(0xffffffffu, den, off);
    }

    if (deg > 0) {
        float inv = 1.f / den;
        acc.x *= inv;
        acc.y *= inv;
    }
    // fused ELU; zero-degree nodes write elu(0)=0
    acc.x = (acc.x > 0.f) ? acc.x : expm1f(acc.x);
    acc.y = (acc.y > 0.f) ? acc.y : expm1f(acc.y);
    *(float2*)(out + (size_t)node * OUT_DIM + lane * 2) = acc;
}

// ---------------- launch ----------------
extern "C" void kernel_launch(void* const* d_in, const int* in_sizes, int n_in,
                              void* d_out, int out_size) {
    const float* h   = (const float*)d_in[0];
    const int*   src = (const int*)d_in[1];
    const int*   dst = (const int*)d_in[2];
    const float* W   = (const float*)d_in[3];
    const float* a   = (const float*)d_in[4];
    float* out = (float*)d_out;

    int N = in_sizes[0] / IN_DIM;   // 100000
    int E = in_sizes[1];            // 1600000

    int NGB = (N + 127) / 128;      // 782 gemm blocks
    int NBK = (NGB + 1) / 2;        // 391 bucket blocks
    int TOTAL = NGB + NBK;          // 1173 (pattern: idx%3==2 -> bucket)

    int smem_bytes = (192 * ASTR + 128) * sizeof(float);  // ~101.9 KB
    cudaFuncSetAttribute(k_gemm_bucket, cudaFuncAttributeMaxDynamicSharedMemorySize, smem_bytes);

    k_zero<<<128, 256>>>(N);
    k_gemm_bucket<<<TOTAL, 256, smem_bytes>>>(h, W, a, src, dst, N, E, NGB, NBK);
    k_node<<<(N * 32 + 255) / 256, 256>>>(out, N);
}

// round 15
// speedup vs baseline: 1.9115x; 1.0179x over previous
#include <cuda_runtime.h>
#include <cuda_fp16.h>
#include <math.h>
#include <stdint.h>

#define NN 100000
#define EE 1600000
#define IN_DIM 128
#define OUT_DIM 64
#define ASTR 132   // padded row stride (floats): conflict-free fragment LDS, 16B-aligned rows
#define CAP 64     // padded-CSR capacity per node (P(deg>=64) ~ 2e-22 for Poisson(16))

// ---------------- scratch (static __device__, no allocs; zero-initialized) ----------------
__device__ __align__(16) __half g_zh[(size_t)NN * OUT_DIM]; // 12.8 MB (z in fp16)
__device__ float g_ss[NN];                 // s_src per node
__device__ float g_sd[NN];                 // s_dst per node
__device__ int   g_cnt[NN];                // per-dst degree (atomic cursor); zeroed by k_zero
__device__ int   g_pad[(size_t)NN * CAP];  // padded CSR: src ids per dst (25.6 MB)

// ---------------- helpers ----------------
__device__ __forceinline__ uint32_t f2tf32(float x) {
    uint32_t u;
    asm("cvt.rna.tf32.f32 %0, %1;" : "=r"(u) : "f"(x));
    return u;
}

__device__ __forceinline__ void mma_tf32(float c[4], uint32_t a0, uint32_t a1,
                                         uint32_t a2, uint32_t a3,
                                         uint32_t b0, uint32_t b1) {
    asm volatile(
        "mma.sync.aligned.m16n8k8.row.col.f32.tf32.tf32.f32 "
        "{%0,%1,%2,%3}, {%4,%5,%6,%7}, {%8,%9}, {%0,%1,%2,%3};"
        : "+f"(c[0]), "+f"(c[1]), "+f"(c[2]), "+f"(c[3])
        : "r"(a0), "r"(a1), "r"(a2), "r"(a3), "r"(b0), "r"(b1));
}

// ---------------- kernels ----------------

__global__ void k_zero(int N) {
    int i = blockIdx.x * blockDim.x + threadIdx.x;
    int stride = gridDim.x * blockDim.x;
    for (; i < N; i += stride) g_cnt[i] = 0;
}

// ---------------- fused GEMM + bucket kernel ----------------
// Role-interleaved blocks: idx%3==2 -> bucket (CSR build), else -> gemm tile.
// The roles use disjoint resources (FMA/smem vs LSU/L2-atomics) and overlap
// across SMs. Bucket loop unrolled 8x: independent LDG->ATOMG->STG chains in
// flight, collapsing the role's latency exposure under the gemm compute.
__global__ __launch_bounds__(256) void k_gemm_bucket(
    const float* __restrict__ h, const float* __restrict__ W,
    const float* __restrict__ a,
    const int* __restrict__ src, const int* __restrict__ dst,
    int N, int E, int NGB, int NBK)
{
    extern __shared__ __align__(16) float smem[];
    int tid = threadIdx.x;
    int idx = blockIdx.x;
    int r = idx % 3;

    if (r == 2) {
        // ---- bucket role: padded-CSR build, grid-stride over edges ----
        int bucket_id = idx / 3;
        if (bucket_id >= NBK) return;
        int stride = NBK * 256;
        #pragma unroll 8
        for (int i = bucket_id * 256 + tid; i < E; i += stride) {
            int d = dst[i];
            int p = atomicAdd(&g_cnt[d], 1);
            if (p < CAP) g_pad[(size_t)d * CAP + p] = src[i];
        }
        return;
    }

    // ---- gemm role ----
    int gemm_id = (idx / 3) * 2 + r;
    if (gemm_id >= NGB) return;

    float* As  = smem;                    // [128][ASTR] tf32 bits
    float* Ws  = smem + 128 * ASTR;       // [64][ASTR]  tf32 bits
    float* ash = smem + 192 * ASTR;       // [128] fp32

    int node0 = gemm_id * 128;

    if (tid < 2 * OUT_DIM) ash[tid] = a[tid];

    // stage A (h rows), converting to tf32
    for (int i = tid; i < 128 * 32; i += 256) {
        int rr = i >> 5;
        int q4 = i & 31;
        int n = node0 + rr;
        float4 v = make_float4(0.f, 0.f, 0.f, 0.f);
        if (n < N) v = *(const float4*)(h + (size_t)n * IN_DIM + q4 * 4);
        float4 t;
        t.x = __uint_as_float(f2tf32(v.x));
        t.y = __uint_as_float(f2tf32(v.y));
        t.z = __uint_as_float(f2tf32(v.z));
        t.w = __uint_as_float(f2tf32(v.w));
        *(float4*)(As + rr * ASTR + q4 * 4) = t;
    }
    // stage B (W rows), converting to tf32
    for (int i = tid; i < 64 * 32; i += 256) {
        int rr = i >> 5;
        int q4 = i & 31;
        float4 v = *(const float4*)(W + (size_t)rr * IN_DIM + q4 * 4);
        float4 t;
        t.x = __uint_as_float(f2tf32(v.x));
        t.y = __uint_as_float(f2tf32(v.y));
        t.z = __uint_as_float(f2tf32(v.z));
        t.w = __uint_as_float(f2tf32(v.w));
        *(float4*)(Ws + rr * ASTR + q4 * 4) = t;
    }
    __syncthreads();

    int wid = tid >> 5;
    int lane = tid & 31;
    int g = lane >> 2;        // groupID: row within fragment
    int tg = lane & 3;        // threadID in group

    float acc[8][4];
    #pragma unroll
    for (int t = 0; t < 8; t++)
        #pragma unroll
        for (int j = 0; j < 4; j++) acc[t][j] = 0.f;

    const float* arow = As + (wid * 16 + g) * ASTR + tg;
    const float* brow = Ws + g * ASTR + tg;

    #pragma unroll
    for (int ks = 0; ks < 16; ks++) {
        int k0 = ks * 8;
        uint32_t a0 = __float_as_uint(arow[k0]);
        uint32_t a1 = __float_as_uint(arow[8 * ASTR + k0]);
        uint32_t a2 = __float_as_uint(arow[k0 + 4]);
        uint32_t a3 = __float_as_uint(arow[8 * ASTR + k0 + 4]);
        #pragma unroll
        for (int t = 0; t < 8; t++) {
            uint32_t b0 = __float_as_uint(brow[t * 8 * ASTR + k0]);
            uint32_t b1 = __float_as_uint(brow[t * 8 * ASTR + k0 + 4]);
            mma_tf32(acc[t], a0, a1, a2, a3, b0, b1);
        }
    }

    // epilogue: rows r0 = node0+16w+g, r1 = r0+8; thread owns cols 8t+2tg, 8t+2tg+1
    int r0 = node0 + wid * 16 + g;
    int r1 = r0 + 8;
    float p0 = 0.f, q0 = 0.f, p1 = 0.f, q1 = 0.f;
    #pragma unroll
    for (int t = 0; t < 8; t++) {
        int c = 8 * t + 2 * tg;
        float av0 = ash[c], av1 = ash[c + 1];
        float bv0 = ash[OUT_DIM + c], bv1 = ash[OUT_DIM + c + 1];
        if (r0 < N) *(__half2*)(g_zh + (size_t)r0 * OUT_DIM + c) =
            __floats2half2_rn(acc[t][0], acc[t][1]);
        if (r1 < N) *(__half2*)(g_zh + (size_t)r1 * OUT_DIM + c) =
            __floats2half2_rn(acc[t][2], acc[t][3]);
        p0 = fmaf(acc[t][0], av0, fmaf(acc[t][1], av1, p0));
        q0 = fmaf(acc[t][0], bv0, fmaf(acc[t][1], bv1, q0));
        p1 = fmaf(acc[t][2], av0, fmaf(acc[t][3], av1, p1));
        q1 = fmaf(acc[t][2], bv0, fmaf(acc[t][3], bv1, q1));
    }
    #pragma unroll
    for (int off = 1; off < 4; off <<= 1) {
        p0 += __shfl_xor_sync(0xffffffffu, p0, off);
        q0 += __shfl_xor_sync(0xffffffffu, q0, off);
        p1 += __shfl_xor_sync(0xffffffffu, p1, off);
        q1 += __shfl_xor_sync(0xffffffffu, q1, off);
    }
    if (tg == 0) {
        if (r0 < N) { g_ss[r0] = p0; g_sd[r0] = q0; }
        if (r1 < N) { g_ss[r1] = p1; g_sd[r1] = q1; }
    }
}

// ---------------- aggregation kernel (R10-proven version, NO g_cnt reset) ----------------
// one warp per dst node: softmax (no max-shift needed: |score| <~ 2) +
// weighted aggregation + ELU; single gather pass, no atomics
__global__ __launch_bounds__(256) void k_node(float* __restrict__ out, int N)
{
    int warp = (blockIdx.x * blockDim.x + threadIdx.x) >> 5;
    int lane = threadIdx.x & 31;
    if (warp >= N) return;
    int node = warp;
    int deg = min(g_cnt[node], CAP);
    const int* lst = g_pad + (size_t)node * CAP;
    float2 acc = make_float2(0.f, 0.f);
    float den = 0.f;

    if (deg > 0 && deg <= 32) {
        // fast path: whole segment resident in one warp pass
        float sd = g_sd[node];
        bool act = lane < deg;
        int sreg = act ? lst[lane] : 0;
        float v = act ? g_ss[sreg] + sd : 0.f;
        v = (v >= 0.f) ? v : 0.01f * v;
        float ex = act ? __expf(v) : 0.f;
        den = ex;
        #pragma unroll
        for (int off = 16; off; off >>= 1)
            den += __shfl_xor_sync(0xffffffffu, den, off);
        #pragma unroll 8
        for (int j = 0; j < deg; j++) {
            int s = __shfl_sync(0xffffffffu, sreg, j);
            float ej = __shfl_sync(0xffffffffu, ex, j);
            float2 zv = __half22float2(*(const __half2*)(g_zh + (size_t)s * OUT_DIM + lane * 2));
            acc.x = fmaf(ej, zv.x, acc.x);
            acc.y = fmaf(ej, zv.y, acc.y);
        }
    } else if (deg > 32) {
        // single combined pass: denom + weighted accumulation
        float sd = g_sd[node];
        float denl = 0.f;
        for (int base = 0; base < deg; base += 32) {
            int i = base + lane;
            int sreg = 0;
            float ex = 0.f;
            if (i < deg) {
                sreg = lst[i];
                float v = g_ss[sreg] + sd;
                v = (v >= 0.f) ? v : 0.01f * v;
                ex = __expf(v);
                denl += ex;
            }
            int cnt = min(32, deg - base);
            #pragma unroll 8
            for (int j = 0; j < cnt; j++) {
                int s = __shfl_sync(0xffffffffu, sreg, j);
                float ej = __shfl_sync(0xffffffffu, ex, j);
                float2 zv = __half22float2(*(const __half2*)(g_zh + (size_t)s * OUT_DIM + lane * 2));
                acc.x = fmaf(ej, zv.x, acc.x);
                acc.y = fmaf(ej, zv.y, acc.y);
            }
        }
        den = denl;
        #pragma unroll
        for (int off = 16; off; off >>= 1)
            den += __shfl_xor_sync(0xffffffffu, den, off);
    }

    if (deg > 0) {
        float inv = 1.f / den;
        acc.x *= inv;
        acc.y *= inv;
    }
    // fused ELU; zero-degree nodes write elu(0)=0
    acc.x = (acc.x > 0.f) ? acc.x : expm1f(acc.x);
    acc.y = (acc.y > 0.f) ? acc.y : expm1f(acc.y);
    *(float2*)(out + (size_t)node * OUT_DIM + lane * 2) = acc;
}

// ---------------- launch ----------------
extern "C" void kernel_launch(void* const* d_in, const int* in_sizes, int n_in,
                              void* d_out, int out_size) {
    const float* h   = (const float*)d_in[0];
    const int*   src = (const int*)d_in[1];
    const int*   dst = (const int*)d_in[2];
    const float* W   = (const float*)d_in[3];
    const float* a   = (const float*)d_in[4];
    float* out = (float*)d_out;

    int N = in_sizes[0] / IN_DIM;   // 100000
    int E = in_sizes[1];            // 1600000

    int NGB = (N + 127) / 128;      // 782 gemm blocks
    int NBK = (NGB + 1) / 2;        // 391 bucket blocks
    int TOTAL = NGB + NBK;          // 1173 (pattern: idx%3==2 -> bucket)

    int smem_bytes = (192 * ASTR + 128) * sizeof(float);  // ~101.9 KB
    cudaFuncSetAttribute(k_gemm_bucket, cudaFuncAttributeMaxDynamicSharedMemorySize, smem_bytes);

    k_zero<<<128, 256>>>(N);
    k_gemm_bucket<<<TOTAL, 256, smem_bytes>>>(h, W, a, src, dst, N, E, NGB, NBK);
    k_node<<<(N * 32 + 255) / 256, 256>>>(out, N);
}

// round 16
// speedup vs baseline: 1.9878x; 1.0399x over previous
#include <cuda_runtime.h>
#include <math.h>
#include <stdint.h>

#define NN 100000
#define EE 1600000
#define IN_DIM 128
#define OUT_DIM 64
#define ASTR 132   // padded row stride (floats): conflict-free fragment LDS, 16B-aligned rows
#define CAP 64     // padded-CSR capacity per node (P(deg>=64) ~ 1e-17 union bound, Poisson(16))

// ---------------- scratch (static __device__, no allocs; zero-initialized) ----------------
__device__ __align__(16) float g_z[(size_t)NN * OUT_DIM];  // 25.6 MB (z in fp32)
__device__ float g_ss[NN];                 // s_src per node
__device__ float g_sd[NN];                 // s_dst per node
__device__ int   g_cnt[NN];                // per-dst degree (atomic cursor); zeroed by k_zero
__device__ int   g_pad[(size_t)NN * CAP];  // padded CSR: src ids per dst (25.6 MB)

// ---------------- helpers ----------------
__device__ __forceinline__ uint32_t f2tf32(float x) {
    uint32_t u;
    asm("cvt.rna.tf32.f32 %0, %1;" : "=r"(u) : "f"(x));
    return u;
}

__device__ __forceinline__ void mma_tf32(float c[4], uint32_t a0, uint32_t a1,
                                         uint32_t a2, uint32_t a3,
                                         uint32_t b0, uint32_t b1) {
    asm volatile(
        "mma.sync.aligned.m16n8k8.row.col.f32.tf32.tf32.f32 "
        "{%0,%1,%2,%3}, {%4,%5,%6,%7}, {%8,%9}, {%0,%1,%2,%3};"
        : "+f"(c[0]), "+f"(c[1]), "+f"(c[2]), "+f"(c[3])
        : "r"(a0), "r"(a1), "r"(a2), "r"(a3), "r"(b0), "r"(b1));
}

// ---------------- kernels ----------------

__global__ void k_zero(int N) {
    int i = blockIdx.x * blockDim.x + threadIdx.x;
    int stride = gridDim.x * blockDim.x;
    for (; i < N; i += stride) g_cnt[i] = 0;
}

// z = h @ W^T via tf32 mma.sync; fused s_src/s_dst epilogue; z stored fp32.
// Block: 128 nodes x 64 outs; warp w owns rows 16w..16w+15, all 64 cols.
__global__ __launch_bounds__(256) void k_gemm_mma(
    const float* __restrict__ h, const float* __restrict__ W,
    const float* __restrict__ a, int N)
{
    extern __shared__ __align__(16) float smem[];
    float* As  = smem;                    // [128][ASTR] tf32 bits
    float* Ws  = smem + 128 * ASTR;       // [64][ASTR]  tf32 bits
    float* ash = smem + 192 * ASTR;       // [128] fp32

    int tid = threadIdx.x;
    int node0 = blockIdx.x * 128;

    if (tid < 2 * OUT_DIM) ash[tid] = a[tid];

    // stage A (h rows), converting to tf32
    for (int i = tid; i < 128 * 32; i += 256) {
        int rr = i >> 5;
        int q4 = i & 31;
        int n = node0 + rr;
        float4 v = make_float4(0.f, 0.f, 0.f, 0.f);
        if (n < N) v = *(const float4*)(h + (size_t)n * IN_DIM + q4 * 4);
        float4 t;
        t.x = __uint_as_float(f2tf32(v.x));
        t.y = __uint_as_float(f2tf32(v.y));
        t.z = __uint_as_float(f2tf32(v.z));
        t.w = __uint_as_float(f2tf32(v.w));
        *(float4*)(As + rr * ASTR + q4 * 4) = t;
    }
    // stage B (W rows), converting to tf32
    for (int i = tid; i < 64 * 32; i += 256) {
        int rr = i >> 5;
        int q4 = i & 31;
        float4 v = *(const float4*)(W + (size_t)rr * IN_DIM + q4 * 4);
        float4 t;
        t.x = __uint_as_float(f2tf32(v.x));
        t.y = __uint_as_float(f2tf32(v.y));
        t.z = __uint_as_float(f2tf32(v.z));
        t.w = __uint_as_float(f2tf32(v.w));
        *(float4*)(Ws + rr * ASTR + q4 * 4) = t;
    }
    __syncthreads();

    int wid = tid >> 5;
    int lane = tid & 31;
    int g = lane >> 2;        // groupID: row within fragment
    int tg = lane & 3;        // threadID in group

    float acc[8][4];
    #pragma unroll
    for (int t = 0; t < 8; t++)
        #pragma unroll
        for (int j = 0; j < 4; j++) acc[t][j] = 0.f;

    const float* arow = As + (wid * 16 + g) * ASTR + tg;
    const float* brow = Ws + g * ASTR + tg;

    #pragma unroll
    for (int ks = 0; ks < 16; ks++) {
        int k0 = ks * 8;
        uint32_t a0 = __float_as_uint(arow[k0]);
        uint32_t a1 = __float_as_uint(arow[8 * ASTR + k0]);
        uint32_t a2 = __float_as_uint(arow[k0 + 4]);
        uint32_t a3 = __float_as_uint(arow[8 * ASTR + k0 + 4]);
        #pragma unroll
        for (int t = 0; t < 8; t++) {
            uint32_t b0 = __float_as_uint(brow[t * 8 * ASTR + k0]);
            uint32_t b1 = __float_as_uint(brow[t * 8 * ASTR + k0 + 4]);
            mma_tf32(acc[t], a0, a1, a2, a3, b0, b1);
        }
    }

    // epilogue: rows r0 = node0+16w+g, r1 = r0+8; thread owns cols 8t+2tg, 8t+2tg+1
    int r0 = node0 + wid * 16 + g;
    int r1 = r0 + 8;
    float p0 = 0.f, q0 = 0.f, p1 = 0.f, q1 = 0.f;
    #pragma unroll
    for (int t = 0; t < 8; t++) {
        int c = 8 * t + 2 * tg;
        float av0 = ash[c], av1 = ash[c + 1];
        float bv0 = ash[OUT_DIM + c], bv1 = ash[OUT_DIM + c + 1];
        if (r0 < N) *(float2*)(g_z + (size_t)r0 * OUT_DIM + c) =
            make_float2(acc[t][0], acc[t][1]);
        if (r1 < N) *(float2*)(g_z + (size_t)r1 * OUT_DIM + c) =
            make_float2(acc[t][2], acc[t][3]);
        p0 = fmaf(acc[t][0], av0, fmaf(acc[t][1], av1, p0));
        q0 = fmaf(acc[t][0], bv0, fmaf(acc[t][1], bv1, q0));
        p1 = fmaf(acc[t][2], av0, fmaf(acc[t][3], av1, p1));
        q1 = fmaf(acc[t][2], bv0, fmaf(acc[t][3], bv1, q1));
    }
    #pragma unroll
    for (int off = 1; off < 4; off <<= 1) {
        p0 += __shfl_xor_sync(0xffffffffu, p0, off);
        q0 += __shfl_xor_sync(0xffffffffu, q0, off);
        p1 += __shfl_xor_sync(0xffffffffu, p1, off);
        q1 += __shfl_xor_sync(0xffffffffu, q1, off);
    }
    if (tg == 0) {
        if (r0 < N) { g_ss[r0] = p0; g_sd[r0] = q0; }
        if (r1 < N) { g_ss[r1] = p1; g_sd[r1] = q1; }
    }
}

// padded-CSR build: single pass, atomic cursor doubles as degree count
__global__ void k_bucket(const int* __restrict__ src, const int* __restrict__ dst, int E) {
    int i = blockIdx.x * blockDim.x + threadIdx.x;
    if (i < E) {
        int d = dst[i];
        int p = atomicAdd(&g_cnt[d], 1);
        if (p < CAP) g_pad[(size_t)d * CAP + p] = src[i];
    }
}

// ---------------- aggregation (R10 structure, z in fp32 -> no cvt in inner loop) ----------------
// one warp per dst node: softmax (no max-shift needed: |score| <~ 2) +
// weighted aggregation + ELU; single gather pass, no atomics, no prologue stores
__global__ __launch_bounds__(256) void k_node(float* __restrict__ out, int N)
{
    int warp = (blockIdx.x * blockDim.x + threadIdx.x) >> 5;
    int lane = threadIdx.x & 31;
    if (warp >= N) return;
    int node = warp;
    int deg = min(g_cnt[node], CAP);
    const int* lst = g_pad + (size_t)node * CAP;
    float2 acc = make_float2(0.f, 0.f);
    float den = 0.f;

    if (deg > 0 && deg <= 32) {
        // fast path: whole segment resident in one warp pass
        float sd = g_sd[node];
        bool act = lane < deg;
        int sreg = act ? lst[lane] : 0;
        float v = act ? g_ss[sreg] + sd : 0.f;
        v = (v >= 0.f) ? v : 0.01f * v;
        float ex = act ? __expf(v) : 0.f;
        den = ex;
        #pragma unroll
        for (int off = 16; off; off >>= 1)
            den += __shfl_xor_sync(0xffffffffu, den, off);
        #pragma unroll 8
        for (int j = 0; j < deg; j++) {
            int s = __shfl_sync(0xffffffffu, sreg, j);
            float ej = __shfl_sync(0xffffffffu, ex, j);
            float2 zv = *(const float2*)(g_z + (size_t)s * OUT_DIM + lane * 2);
            acc.x = fmaf(ej, zv.x, acc.x);
            acc.y = fmaf(ej, zv.y, acc.y);
        }
    } else if (deg > 32) {
        // single combined pass: denom + weighted accumulation
        float sd = g_sd[node];
        float denl = 0.f;
        for (int base = 0; base < deg; base += 32) {
            int i = base + lane;
            int sreg = 0;
            float ex = 0.f;
            if (i < deg) {
                sreg = lst[i];
                float v = g_ss[sreg] + sd;
                v = (v >= 0.f) ? v : 0.01f * v;
                ex = __expf(v);
                denl += ex;
            }
            int cnt = min(32, deg - base);
            #pragma unroll 8
            for (int j = 0; j < cnt; j++) {
                int s = __shfl_sync(0xffffffffu, sreg, j);
                float ej = __shfl_sync(0xffffffffu, ex, j);
                float2 zv = *(const float2*)(g_z + (size_t)s * OUT_DIM + lane * 2);
                acc.x = fmaf(ej, zv.x, acc.x);
                acc.y = fmaf(ej, zv.y, acc.y);
            }
        }
        den = denl;
        #pragma unroll
        for (int off = 16; off; off >>= 1)
            den += __shfl_xor_sync(0xffffffffu, den, off);
    }

    if (deg > 0) {
        float inv = 1.f / den;
        acc.x *= inv;
        acc.y *= inv;
    }
    // fused ELU; zero-degree nodes write elu(0)=0
    acc.x = (acc.x > 0.f) ? acc.x : expm1f(acc.x);
    acc.y = (acc.y > 0.f) ? acc.y : expm1f(acc.y);
    *(float2*)(out + (size_t)node * OUT_DIM + lane * 2) = acc;
}

// ---------------- launch ----------------
extern "C" void kernel_launch(void* const* d_in, const int* in_sizes, int n_in,
                              void* d_out, int out_size) {
    const float* h   = (const float*)d_in[0];
    const int*   src = (const int*)d_in[1];
    const int*   dst = (const int*)d_in[2];
    const float* W   = (const float*)d_in[3];
    const float* a   = (const float*)d_in[4];
    float* out = (float*)d_out;

    int N = in_sizes[0] / IN_DIM;   // 100000
    int E = in_sizes[1];            // 1600000

    int smem_bytes = (192 * ASTR + 128) * sizeof(float);  // ~101.9 KB
    cudaFuncSetAttribute(k_gemm_mma, cudaFuncAttributeMaxDynamicSharedMemorySize, smem_bytes);

    k_zero<<<128, 256>>>(N);
    k_gemm_mma<<<(N + 127) / 128, 256, smem_bytes>>>(h, W, a, N);
    k_bucket<<<(E + 511) / 512, 512>>>(src, dst, E);
    k_node<<<(N * 32 + 255) / 256, 256>>>(out, N);
}